// round 1
// baseline (speedup 1.0000x reference)
#include <cuda_runtime.h>
#include <cstdint>

#define HW   128
#define CIN  16
#define OOUT 64

// A[i,k] = Re(P_i[r,c]), r=k/4, c=k%4 ; P_i = 15 non-identity 2-qubit Paulis in
// (I,X,Y,Z)x(I,X,Y,Z) order (skipping I(x)I). Rows with any Y-odd factor are 0.
__constant__ float c_A[15][9] = {
  {0,1,0,0,1,0,0,0,0},    // I X
  {0,0,0,0,0,0,0,0,0},    // I Y
  {1,0,0,0,0,-1,0,0,0},   // I Z
  {0,0,1,0,0,0,0,1,1},    // X I
  {0,0,0,1,0,0,1,0,0},    // X X
  {0,0,0,0,0,0,0,0,0},    // X Y
  {0,0,1,0,0,0,0,-1,1},   // X Z
  {0,0,0,0,0,0,0,0,0},    // Y I
  {0,0,0,0,0,0,0,0,0},    // Y X
  {0,0,0,-1,0,0,1,0,0},   // Y Y
  {0,0,0,0,0,0,0,0,0},    // Y Z
  {1,0,0,0,0,1,0,0,0},    // Z I
  {0,1,0,0,1,0,0,0,0},    // Z X
  {0,0,0,0,0,0,0,0,0},    // Z Y
  {1,0,0,0,0,-1,0,0,0},   // Z Z
};
__constant__ float c_t0[9] = {1,0,0,0,0,1,0,0,0};

// Folded conv weights: g_W3[(c*9+k)*64 + o] = 0.25*(t0[k] + sum_i weight[o,c,i]*A[i,k])
__device__ float g_W3[CIN * 9 * OOUT];

__global__ void prep_weights(const float* __restrict__ w) {
  int idx = blockIdx.x * 256 + threadIdx.x;
  if (idx >= CIN * 9 * OOUT) return;
  int o = idx & 63;
  int k = (idx >> 6) % 9;
  int c = idx / (64 * 9);
  float s = c_t0[k];
#pragma unroll
  for (int i = 0; i < 15; i++) s += w[(o * CIN + c) * 15 + i] * c_A[i][k];
  g_W3[idx] = 0.25f * s;
}

// ---- packed f32x2 helpers (Blackwell: 2x fp32 FMA throughput vs 3-reg FFMA) ----
__device__ __forceinline__ unsigned long long pk2(float lo, float hi) {
  unsigned long long r;
  asm("mov.b64 %0, {%1, %2};" : "=l"(r) : "f"(lo), "f"(hi));
  return r;
}
__device__ __forceinline__ unsigned long long fma2(unsigned long long a,
                                                   unsigned long long b,
                                                   unsigned long long c) {
  unsigned long long d;
  asm("fma.rn.f32x2 %0, %1, %2, %3;" : "=l"(d) : "l"(a), "l"(b), "l"(c));
  return d;
}
__device__ __forceinline__ void upk(unsigned long long v, float& lo, float& hi) {
  asm("mov.b64 {%0, %1}, %2;" : "=f"(lo), "=f"(hi) : "l"(v));
}

// SMEM layout
#define XS_STRIDE 20                       // padded row dim (16B-aligned columns)
#define XS_COLS   18
#define XS_PER_C  (XS_COLS * XS_STRIDE)    // 360 floats
#define XS_TOTAL  (CIN * XS_PER_C)         // 5760 floats
#define WS_TOTAL  (CIN * 9 * OOUT)         // 9216 floats
#define SMEM_BYTES ((XS_TOTAL + WS_TOTAL) * 4)  // 59904 B

// Block: 256 threads = 8 o-groups (warps) x 32 pixel-threads.
// Pixel-thread: col = lane&15, rows (lane>>4)*8 .. +7 of a 16x16 output tile.
// Thread computes 8 out-channels x 8 pixels = 32 f32x2 accumulators.
__global__ void __launch_bounds__(256, 2)
conv3x3(const float* __restrict__ x, const float* __restrict__ bias,
        float* __restrict__ out) {
  extern __shared__ float smem[];
  float* xs = smem;              // [c][col 0..17][row 0..17 (pad 20)]  (transposed tile)
  float* ws = smem + XS_TOTAL;   // [c][k][o]

  const int tid = threadIdx.x;
  const int b  = blockIdx.z;
  const int ht = blockIdx.y * 16;
  const int wt = blockIdx.x * 16;

  // stage folded weights
  for (int i = tid; i < WS_TOTAL; i += 256) ws[i] = g_W3[i];

  // stage x halo tile (18x18 per channel, zero-padded at image borders),
  // stored transposed: xs[c][col][row]
  const float* xb = x + ((size_t)b * CIN) * (HW * HW);
  for (int i = tid; i < CIN * 324; i += 256) {
    int c   = i / 324;
    int rc  = i - c * 324;
    int row = rc / 18;          // -> h = ht + row - 1
    int col = rc - row * 18;    // -> w = wt + col - 1
    int h = ht + row - 1;
    int w = wt + col - 1;
    float v = 0.f;
    if ((unsigned)h < (unsigned)HW && (unsigned)w < (unsigned)HW)
      v = xb[(c * HW + h) * HW + w];
    xs[c * XS_PER_C + col * XS_STRIDE + row] = v;
  }
  __syncthreads();

  const int lane = tid & 31;
  const int og   = tid >> 5;          // o-group: channels og*8 .. og*8+7
  const int colp = lane & 15;         // output column within tile
  const int rb   = (lane >> 4) << 3;  // output row base: 0 or 8

  unsigned long long acc[8][4];
#pragma unroll
  for (int oi = 0; oi < 8; oi++)
#pragma unroll
    for (int t = 0; t < 4; t++) acc[oi][t] = 0ull;

#pragma unroll 1
  for (int c = 0; c < CIN; c++) {
    const float* xc = xs + c * XS_PER_C;
    const float* wc = ws + c * 9 * 64 + og * 8;
#pragma unroll
    for (int kw = 0; kw < 3; kw++) {
      // 12-row strip for this (c, col+kw): 3x LDS.128, conflict-free
      const float4* xp = (const float4*)(xc + (colp + kw) * XS_STRIDE + rb);
      float4 a0 = xp[0], a1 = xp[1], a2 = xp[2];
      float xv[12] = {a0.x, a0.y, a0.z, a0.w, a1.x, a1.y, a1.z, a1.w,
                      a2.x, a2.y, a2.z, a2.w};
#pragma unroll
      for (int kh = 0; kh < 3; kh++) {
        const float4* wp = (const float4*)(wc + (kh * 3 + kw) * 64);
        float4 w0 = wp[0], w1 = wp[1];  // broadcast LDS
        float wv[8] = {w0.x, w0.y, w0.z, w0.w, w1.x, w1.y, w1.z, w1.w};
        unsigned long long px[4];
#pragma unroll
        for (int t = 0; t < 4; t++)
          px[t] = pk2(xv[kh + 2 * t], xv[kh + 2 * t + 1]);
#pragma unroll
        for (int oi = 0; oi < 8; oi++) {
          unsigned long long wd = pk2(wv[oi], wv[oi]);
#pragma unroll
          for (int t = 0; t < 4; t++) acc[oi][t] = fma2(wd, px[t], acc[oi][t]);
        }
      }
    }
  }

  // epilogue: unpack pairs (rows 2t, 2t+1), add bias, store
  float* ob = out + ((size_t)b * OOUT) * (HW * HW);
#pragma unroll
  for (int oi = 0; oi < 8; oi++) {
    int o = og * 8 + oi;
    float bo = __ldg(&bias[o]);
#pragma unroll
    for (int t = 0; t < 4; t++) {
      float lo, hi;
      upk(acc[oi][t], lo, hi);
      int h = ht + rb + 2 * t;
      ob[((size_t)o * HW + h) * HW + (wt + colp)]     = lo + bo;
      ob[((size_t)o * HW + h + 1) * HW + (wt + colp)] = hi + bo;
    }
  }
}

extern "C" void kernel_launch(void* const* d_in, const int* in_sizes, int n_in,
                              void* d_out, int out_size) {
  const float* x    = (const float*)d_in[0];  // [32,16,128,128]
  const float* w    = (const float*)d_in[1];  // [64,16,15]
  const float* bias = (const float*)d_in[2];  // [64,1]
  float* out = (float*)d_out;                 // [32,64,128,128]

  cudaFuncSetAttribute(conv3x3, cudaFuncAttributeMaxDynamicSharedMemorySize,
                       SMEM_BYTES);

  prep_weights<<<(CIN * 9 * OOUT + 255) / 256, 256>>>(w);
  conv3x3<<<dim3(HW / 16, HW / 16, 32), 256, SMEM_BYTES>>>(x, bias, out);
}

// round 2
// speedup vs baseline: 1.0664x; 1.0664x over previous
#include <cuda_runtime.h>
#include <cstdint>

#define HW   128
#define CIN  16
#define OOUT 64

// A[i,k] = Re(P_i[r,c]), r=k/4, c=k%4 ; 15 non-identity 2-qubit Paulis,
// (I,X,Y,Z)x(I,X,Y,Z) order minus I(x)I. Rows with an odd number of Y factors are 0.
__constant__ float c_A[15][9] = {
  {0,1,0,0,1,0,0,0,0},    // I X
  {0,0,0,0,0,0,0,0,0},    // I Y
  {1,0,0,0,0,-1,0,0,0},   // I Z
  {0,0,1,0,0,0,0,1,1},    // X I
  {0,0,0,1,0,0,1,0,0},    // X X
  {0,0,0,0,0,0,0,0,0},    // X Y
  {0,0,1,0,0,0,0,-1,1},   // X Z
  {0,0,0,0,0,0,0,0,0},    // Y I
  {0,0,0,0,0,0,0,0,0},    // Y X
  {0,0,0,-1,0,0,1,0,0},   // Y Y
  {0,0,0,0,0,0,0,0,0},    // Y Z
  {1,0,0,0,0,1,0,0,0},    // Z I
  {0,1,0,0,1,0,0,0,0},    // Z X
  {0,0,0,0,0,0,0,0,0},    // Z Y
  {1,0,0,0,0,-1,0,0,0},   // Z Z
};
__constant__ float c_t0[9] = {1,0,0,0,0,1,0,0,0};

// Folded conv weights: g_W3[(c*9+k)*64 + o] = 0.25*(t0[k] + sum_i weight[o,c,i]*A[i,k])
__device__ float g_W3[CIN * 9 * OOUT];

__global__ void prep_weights(const float* __restrict__ w) {
  int idx = blockIdx.x * 256 + threadIdx.x;
  if (idx >= CIN * 9 * OOUT) return;
  int o = idx & 63;
  int k = (idx >> 6) % 9;
  int c = idx / (64 * 9);
  float s = c_t0[k];
#pragma unroll
  for (int i = 0; i < 15; i++) s += w[(o * CIN + c) * 15 + i] * c_A[i][k];
  g_W3[idx] = 0.25f * s;
}

__device__ __forceinline__ unsigned long long fma2(unsigned long long a,
                                                   unsigned long long b,
                                                   unsigned long long c) {
  unsigned long long d;
  asm("fma.rn.f32x2 %0, %1, %2, %3;" : "=l"(d) : "l"(a), "l"(b), "l"(c));
  return d;
}
__device__ __forceinline__ void upk(unsigned long long v, float& lo, float& hi) {
  asm("mov.b64 {%0, %1}, %2;" : "=f"(lo), "=f"(hi) : "l"(v));
}

// SMEM layout
// xs: x halo tile, DUPLICATED pairs (v,v), transposed: [c][col 0..17][row 0..17]
//     stride per col = 18 rows * 2 floats = 36 floats (144B: 16B-aligned, 4-bank
//     shift per lane -> conflict-free LDS.128)
#define XS_PER_C  (18 * 36)                // 648 floats
#define XS_TOTAL  (CIN * XS_PER_C)         // 10368 floats
#define WS_TOTAL  (CIN * 9 * OOUT)         // 9216 floats
#define SMEM_BYTES ((XS_TOTAL + WS_TOTAL) * 4)  // 78336 B

// Block: 256 threads = 8 o-groups (warps) x 32 pixel-threads.
// Pixel-thread: col = lane&15, rows (lane>>4)*8 .. +7 of the 16x16 output tile.
// Accumulators pair OUTPUT CHANNELS: acc[op][r] = (out[o2op], out[o2op+1]) at row r.
__global__ void __launch_bounds__(256, 2)
conv3x3(const float* __restrict__ x, const float* __restrict__ bias,
        float* __restrict__ out) {
  extern __shared__ float smem[];
  float* xs = smem;
  float* ws = smem + XS_TOTAL;   // [c][k][o]

  const int tid = threadIdx.x;
  const int b  = blockIdx.z;
  const int ht = blockIdx.y * 16;
  const int wt = blockIdx.x * 16;

  // stage folded weights
  for (int i = tid; i < WS_TOTAL; i += 256) ws[i] = g_W3[i];

  // stage x halo tile (18x18 per channel, zero-padded), duplicated + transposed
  const float* xb = x + ((size_t)b * CIN) * (HW * HW);
  for (int i = tid; i < CIN * 324; i += 256) {
    int c   = i / 324;
    int rc  = i - c * 324;
    int row = rc / 18;          // h = ht + row - 1
    int col = rc - row * 18;    // w = wt + col - 1
    int h = ht + row - 1;
    int w = wt + col - 1;
    float v = 0.f;
    if ((unsigned)h < (unsigned)HW && (unsigned)w < (unsigned)HW)
      v = xb[(c * HW + h) * HW + w];
    float2* dst = (float2*)(xs + c * XS_PER_C + col * 36 + row * 2);
    *dst = make_float2(v, v);
  }
  __syncthreads();

  const int lane = tid & 31;
  const int og   = tid >> 5;          // this warp's 8 out-channels: og*8..og*8+7
  const int colp = lane & 15;
  const int rb   = (lane >> 4) << 3;  // row base 0 or 8

  unsigned long long acc[4][8];       // [o-pair][row]
#pragma unroll
  for (int op = 0; op < 4; op++)
#pragma unroll
    for (int r = 0; r < 8; r++) acc[op][r] = 0ull;

#pragma unroll 1
  for (int c = 0; c < CIN; c++) {
    const float* xc = xs + c * XS_PER_C;
    const float* wc = ws + c * 9 * 64 + og * 8;
#pragma unroll
    for (int kw = 0; kw < 3; kw++) {
      // 10 duplicated row-pairs (rows rb..rb+9) = 5x LDS.128
      const ulonglong2* xp =
          (const ulonglong2*)(xc + (colp + kw) * 36 + rb * 2);
      unsigned long long p[10];
#pragma unroll
      for (int j = 0; j < 5; j++) {
        ulonglong2 v = xp[j];
        p[2 * j]     = v.x;
        p[2 * j + 1] = v.y;
      }
#pragma unroll
      for (int kh = 0; kh < 3; kh++) {
        const ulonglong2* wp =
            (const ulonglong2*)(wc + (kh * 3 + kw) * 64);
        ulonglong2 wa = wp[0], wb = wp[1];
        unsigned long long wd[4] = {wa.x, wa.y, wb.x, wb.y};
#pragma unroll
        for (int op = 0; op < 4; op++)
#pragma unroll
          for (int r = 0; r < 8; r++)
            acc[op][r] = fma2(wd[op], p[kh + r], acc[op][r]);
      }
    }
  }

  // epilogue: unpack (o_even, o_odd), add bias, store
  float* ob = out + ((size_t)b * OOUT) * (HW * HW);
#pragma unroll
  for (int op = 0; op < 4; op++) {
    int o = og * 8 + op * 2;
    float b0 = __ldg(&bias[o]);
    float b1 = __ldg(&bias[o + 1]);
    float* o0 = ob + ((size_t)o * HW) * HW + wt + colp;
    float* o1 = o0 + (size_t)HW * HW;
#pragma unroll
    for (int r = 0; r < 8; r++) {
      float lo, hi;
      upk(acc[op][r], lo, hi);
      int h = ht + rb + r;
      o0[(size_t)h * HW] = lo + b0;
      o1[(size_t)h * HW] = hi + b1;
    }
  }
}

extern "C" void kernel_launch(void* const* d_in, const int* in_sizes, int n_in,
                              void* d_out, int out_size) {
  const float* x    = (const float*)d_in[0];  // [32,16,128,128]
  const float* w    = (const float*)d_in[1];  // [64,16,15]
  const float* bias = (const float*)d_in[2];  // [64,1]
  float* out = (float*)d_out;                 // [32,64,128,128]

  cudaFuncSetAttribute(conv3x3, cudaFuncAttributeMaxDynamicSharedMemorySize,
                       SMEM_BYTES);

  prep_weights<<<(CIN * 9 * OOUT + 255) / 256, 256>>>(w);
  conv3x3<<<dim3(HW / 16, HW / 16, 32), 256, SMEM_BYTES>>>(x, bias, out);
}

// round 4
// speedup vs baseline: 1.1162x; 1.0467x over previous
#include <cuda_runtime.h>
#include <cuda_bf16.h>
#include <cstdint>

#define HW   128
#define CIN  16
#define OOUT 64
#define Q    390            // 3 * 130 shifted positions
#define XROW 48             // bytes per A-row (16ch * 2B padded to 48 for ldmatrix)
#define XSPLIT (Q * XROW)   // 18720 bytes per split plane

#define SM_XS   0
#define SM_WS   (2 * XSPLIT)          // 37440
#define WS_BYTES 36864                // 18 chunks * 4 * 32 * 16B
#define SM_BIAS (SM_WS + WS_BYTES)    // 74304
#define SMEM_BYTES (SM_BIAS + 256)    // 74560

// A[i,k] = Re(P_i[r,c]), r=k/4, c=k%4 ; 15 non-identity 2-qubit Paulis.
__constant__ float c_A[15][9] = {
  {0,1,0,0,1,0,0,0,0},   {0,0,0,0,0,0,0,0,0},  {1,0,0,0,0,-1,0,0,0},
  {0,0,1,0,0,0,0,1,1},   {0,0,0,1,0,0,1,0,0},  {0,0,0,0,0,0,0,0,0},
  {0,0,1,0,0,0,0,-1,1},  {0,0,0,0,0,0,0,0,0},  {0,0,0,0,0,0,0,0,0},
  {0,0,0,-1,0,0,1,0,0},  {0,0,0,0,0,0,0,0,0},  {1,0,0,0,0,1,0,0,0},
  {0,1,0,0,1,0,0,0,0},   {0,0,0,0,0,0,0,0,0},  {1,0,0,0,0,-1,0,0,0},
};
__constant__ float c_t0[9] = {1,0,0,0,0,1,0,0,0};

// Fragment-linear weights: g_Wf[chunk 18][j2 4][lane 32][8 bf16].
// chunk = wplane*9 + tap. 16B line for lane l = B-fragments of n8-blocks
// (2*j2, 2*j2+1): {b0lo,b0hi,b1lo,b1hi} per block, where for block j:
//   bf16[e]: n = 8*j + l/4 ; k = 2*(l%4) + (e&1) + ((e&2)?8:0)
__device__ __nv_bfloat16 g_Wf[18 * 4 * 32 * 8];

__global__ void prep_weights(const float* __restrict__ w) {
  int idx = blockIdx.x * 256 + threadIdx.x;
  if (idx >= 18432) return;
  int e    = idx & 7;
  int lane = (idx >> 3) & 31;
  int j2   = (idx >> 8) & 3;
  int chunk = idx >> 10;         // 0..17
  int tap = chunk % 9;
  int wp  = chunk / 9;           // 0 = hi, 1 = lo
  int j = 2 * j2 + (e >> 2);
  int n = 8 * j + (lane >> 2);   // out channel o
  int k = 2 * (lane & 3) + (e & 1) + ((e & 2) ? 8 : 0);  // in channel c
  float w3 = c_t0[tap];
#pragma unroll
  for (int i = 0; i < 15; i++) w3 += w[(n * CIN + k) * 15 + i] * c_A[i][tap];
  w3 *= 0.25f;
  __nv_bfloat16 hi = __float2bfloat16(w3);
  g_Wf[idx] = (wp == 0) ? hi : __float2bfloat16(w3 - __bfloat162float(hi));
}

__device__ __forceinline__ uint32_t smem_u32(const void* p) {
  uint32_t a;
  asm("{ .reg .u64 t; cvta.to.shared.u64 t, %1; cvt.u32.u64 %0, t; }"
      : "=r"(a) : "l"(p));
  return a;
}
__device__ __forceinline__ void ldsm4(uint32_t* r, uint32_t addr) {
  asm volatile(
      "ldmatrix.sync.aligned.m8n8.x4.shared.b16 {%0,%1,%2,%3}, [%4];"
      : "=r"(r[0]), "=r"(r[1]), "=r"(r[2]), "=r"(r[3]) : "r"(addr));
}
__device__ __forceinline__ void hmma(float* d, const uint32_t* a, uint32_t b0,
                                     uint32_t b1) {
  asm volatile(
      "mma.sync.aligned.m16n8k16.row.col.f32.bf16.bf16.f32 "
      "{%0,%1,%2,%3}, {%4,%5,%6,%7}, {%8,%9}, {%0,%1,%2,%3};"
      : "+f"(d[0]), "+f"(d[1]), "+f"(d[2]), "+f"(d[3])
      : "r"(a[0]), "r"(a[1]), "r"(a[2]), "r"(a[3]), "r"(b0), "r"(b1));
}

// CTA: 128 threads = 4 warps; output tile M=128 (w), N=64 (oc) for one (b,h).
// Warp tile m32 x n64. K = 3 passes x 9 taps x 16 channels.
__global__ void __launch_bounds__(128, 3)
quanv(const float* __restrict__ x, const float* __restrict__ bias,
      float* __restrict__ out) {
  extern __shared__ char smem[];
  const int tid = threadIdx.x;
  const int lane = tid & 31;
  const int warp = tid >> 5;
  const int h = blockIdx.x;
  const int b = blockIdx.y;

  // stage fragment-linear weights (36864 B)
  {
    const float4* s = (const float4*)g_Wf;
    float4* d = (float4*)(smem + SM_WS);
    for (int i = tid; i < WS_BYTES / 16; i += 128) d[i] = s[i];
  }
  if (tid < 64) ((float*)(smem + SM_BIAS))[tid] = bias[tid];

  // stage x: rows q = dh*130 + pos (pos 0..129 = w -1..128, zero-padded),
  // 16 channels per row, split hi/lo bf16 planes.
  {
    const float* xb = x + (size_t)b * CIN * HW * HW;
    for (int i = tid; i < CIN * Q; i += 128) {
      int c = i / Q, q = i - c * Q;
      int dh = q / 130, pos = q - dh * 130;
      int hs = h + dh - 1, wsr = pos - 1;
      float v = 0.f;
      if ((unsigned)hs < (unsigned)HW && (unsigned)wsr < (unsigned)HW)
        v = xb[(c * HW + hs) * HW + wsr];
      __nv_bfloat16 hi = __float2bfloat16(v);
      __nv_bfloat16 lo = __float2bfloat16(v - __bfloat162float(hi));
      int off = q * XROW + c * 2;
      *(__nv_bfloat16*)(smem + SM_XS + off) = hi;
      *(__nv_bfloat16*)(smem + SM_XS + XSPLIT + off) = lo;
    }
  }
  __syncthreads();

  const uint32_t sb = smem_u32(smem);
  const int mw = warp * 32;
  const uint32_t laneoff = (lane & 15) * XROW + (lane >> 4) * 16;

  float d[2][8][4];
#pragma unroll
  for (int i = 0; i < 2; i++)
#pragma unroll
    for (int j = 0; j < 8; j++)
#pragma unroll
      for (int r = 0; r < 4; r++) d[i][j][r] = 0.f;

  // passes: (x_hi,w_hi), (x_lo,w_hi), (x_hi,w_lo)
#pragma unroll
  for (int pass = 0; pass < 3; pass++) {
    const uint32_t xbase =
        sb + SM_XS + (pass == 1 ? XSPLIT : 0) + mw * XROW + laneoff;
    const uint4* wfp =
        (const uint4*)(smem + SM_WS + (pass == 2 ? 9 * 2048 : 0));
#pragma unroll
    for (int tap = 0; tap < 9; tap++) {
      const int dh = tap / 3, dw = tap - 3 * (tap / 3);
      const uint32_t abase = xbase + (dh * 130 + dw) * XROW;
      uint32_t a0[4], a1[4];
      ldsm4(a0, abase);
      ldsm4(a1, abase + 16 * XROW);
      const uint4* wt = wfp + tap * 128 + lane;
      uint4 bw[4];
#pragma unroll
      for (int j2 = 0; j2 < 4; j2++) bw[j2] = wt[j2 * 32];
#pragma unroll
      for (int j2 = 0; j2 < 4; j2++) {
        hmma(d[0][2 * j2],     a0, bw[j2].x, bw[j2].y);
        hmma(d[0][2 * j2 + 1], a0, bw[j2].z, bw[j2].w);
        hmma(d[1][2 * j2],     a1, bw[j2].x, bw[j2].y);
        hmma(d[1][2 * j2 + 1], a1, bw[j2].z, bw[j2].w);
      }
    }
  }

  // epilogue: fragments -> smem [o][m] (stride 132 floats, conflict-free STS)
  __syncthreads();
  float* ep = (float*)smem;  // 64*132*4 = 33792 B, fits in xs region
#pragma unroll
  for (int i = 0; i < 2; i++)
#pragma unroll
    for (int j = 0; j < 8; j++)
#pragma unroll
      for (int r = 0; r < 4; r++) {
        int m = mw + 16 * i + (lane >> 2) + ((r & 2) ? 8 : 0);
        int o = 8 * j + 2 * (lane & 3) + (r & 1);
        ep[o * 132 + m] = d[i][j][r];
      }
  __syncthreads();

  const float* bs = (const float*)(smem + SM_BIAS);
  float* ob = out + ((size_t)b * OOUT) * (HW * HW) + h * HW;
#pragma unroll
  for (int it = 0; it < 16; it++) {
    int idx = tid + 128 * it;
    int o = idx >> 5, wq = idx & 31;
    float4 v = *(const float4*)(ep + o * 132 + 4 * wq);
    float bo = bs[o];
    v.x += bo; v.y += bo; v.z += bo; v.w += bo;
    *(float4*)(ob + (size_t)o * HW * HW + 4 * wq) = v;
  }
}

extern "C" void kernel_launch(void* const* d_in, const int* in_sizes, int n_in,
                              void* d_out, int out_size) {
  const float* x    = (const float*)d_in[0];  // [32,16,128,128]
  const float* w    = (const float*)d_in[1];  // [64,16,15]
  const float* bias = (const float*)d_in[2];  // [64,1]
  float* out = (float*)d_out;                 // [32,64,128,128]

  cudaFuncSetAttribute(quanv, cudaFuncAttributeMaxDynamicSharedMemorySize,
                       SMEM_BYTES);

  prep_weights<<<(18432 + 255) / 256, 256>>>(w);
  quanv<<<dim3(HW, 32), 128, SMEM_BYTES>>>(x, bias, out);
}